// round 1
// baseline (speedup 1.0000x reference)
#include <cuda_runtime.h>
#include <math.h>

#define BB  512
#define NNt 256
#define DD  128
#define DIi 256
#define NLv 4
#define NSv 16

// ------------------ scratch (device globals; no allocation) ------------------
__device__ float g_X [BB*NNt*DD];          // residual stream
__device__ float g_H [BB*NNt*DD];          // LN output; reused for logits at end
__device__ float g_XZ[BB*NNt*2*DIi];       // in-proj output
__device__ float g_Y [BB*NNt*DIi];         // gated ssm output
__device__ float g_P [NLv*NNt*NSv];        // e^l table
__device__ float g_CF[NLv*NNt*NSv];        // C*dB*e^(L-1-l) table

// ------------------ per-layer SSM coefficient tables ------------------
__global__ void prep_kernel(const float* __restrict__ ssm_B,
                            const float* __restrict__ ssm_C,
                            const float* __restrict__ log_dt) {
    int li = blockIdx.x;
    int l  = threadIdx.x;
    float dt = expf(log_dt[li]);
    dt = fminf(fmaxf(dt, 1e-4f), 1.0f);
    for (int n = 0; n < NSv; n++) {
        float A  = -(float)(n + 1);
        float t  = fminf(fmaxf(dt * A, -10.0f), 10.0f);
        float dA = expf(t);
        float dB = (dA - 1.0f) / fminf(A, -1e-4f) * ssm_B[li*NSv + n];
        g_P [(li*NNt + l)*NSv + n] = expf((float)l * t);
        g_CF[(li*NNt + l)*NSv + n] = ssm_C[li*NSv + n] * dB * expf((float)(NNt - 1 - l) * t);
    }
}

// ------------------ LayerNorm (warp per token), optional pos-add ------------------
__global__ void __launch_bounds__(128) ln_kernel(const float* __restrict__ in,
                                                 const float* __restrict__ pos,
                                                 const float* __restrict__ g,
                                                 const float* __restrict__ b,
                                                 int addPos) {
    int lane = threadIdx.x & 31, w = threadIdx.x >> 5;
    long tk = (long)blockIdx.x * 4 + w;
    float4 v = *(const float4*)(in + tk*DD + lane*4);
    if (addPos) {
        int n = (int)(tk % NNt);
        float4 p = *(const float4*)(pos + (long)n*DD + lane*4);
        v.x += p.x; v.y += p.y; v.z += p.z; v.w += p.w;
        *(float4*)(g_X + tk*DD + lane*4) = v;
    }
    float s = v.x + v.y + v.z + v.w;
#pragma unroll
    for (int o = 16; o > 0; o >>= 1) s += __shfl_xor_sync(0xffffffffu, s, o);
    float m = s * (1.0f/DD);
    float d0 = v.x-m, d1 = v.y-m, d2 = v.z-m, d3 = v.w-m;
    float q = d0*d0 + d1*d1 + d2*d2 + d3*d3;
#pragma unroll
    for (int o = 16; o > 0; o >>= 1) q += __shfl_xor_sync(0xffffffffu, q, o);
    float r = rsqrtf(q * (1.0f/DD) + 1e-5f);
    float4 gg = *(const float4*)(g + lane*4);
    float4 bb = *(const float4*)(b + lane*4);
    float4 o4;
    o4.x = d0*r*gg.x + bb.x;
    o4.y = d1*r*gg.y + bb.y;
    o4.z = d2*r*gg.z + bb.z;
    o4.w = d3*r*gg.w + bb.w;
    *(float4*)(g_H + tk*DD + lane*4) = o4;
}

// ------------------ fp32 SGEMM: C[m,n] = sum_k A[m,k]*W[n,k] (+ resid + scale) ---
__global__ void __launch_bounds__(256) gemm_kernel(const float* __restrict__ A,
                                                   const float* __restrict__ W,
                                                   float* __restrict__ C,
                                                   int K, int N,
                                                   const float* __restrict__ resid,
                                                   const float* __restrict__ rs) {
    __shared__ float As[16][132];
    __shared__ float Bs[16][132];
    int t  = threadIdx.x;
    long m0 = (long)blockIdx.x * 128;
    int  n0 = blockIdx.y * 128;
    int tx = t & 15, ty = t >> 4;
    float acc[8][8];
#pragma unroll
    for (int i = 0; i < 8; i++)
#pragma unroll
        for (int j = 0; j < 8; j++) acc[i][j] = 0.0f;

    for (int k0 = 0; k0 < K; k0 += 16) {
#pragma unroll
        for (int u = 0; u < 2; u++) {
            int v   = t + u*256;
            int row = v >> 2, c4 = v & 3;
            float4 a4 = *(const float4*)(A + (m0 + row)*K + k0 + c4*4);
            As[c4*4+0][row] = a4.x; As[c4*4+1][row] = a4.y;
            As[c4*4+2][row] = a4.z; As[c4*4+3][row] = a4.w;
            float4 b4 = *(const float4*)(W + (long)(n0 + row)*K + k0 + c4*4);
            Bs[c4*4+0][row] = b4.x; Bs[c4*4+1][row] = b4.y;
            Bs[c4*4+2][row] = b4.z; Bs[c4*4+3][row] = b4.w;
        }
        __syncthreads();
#pragma unroll
        for (int kk = 0; kk < 16; kk++) {
            float a[8], bv[8];
            *(float4*)(a)    = *(const float4*)&As[kk][ty*8];
            *(float4*)(a+4)  = *(const float4*)&As[kk][ty*8+4];
            *(float4*)(bv)   = *(const float4*)&Bs[kk][tx*8];
            *(float4*)(bv+4) = *(const float4*)&Bs[kk][tx*8+4];
#pragma unroll
            for (int i = 0; i < 8; i++)
#pragma unroll
                for (int j = 0; j < 8; j++) acc[i][j] += a[i]*bv[j];
        }
        __syncthreads();
    }
    float scale = 0.0f;
    if (resid) scale = fminf(fmaxf(rs[0], 0.0f), 1.5f);
#pragma unroll
    for (int i = 0; i < 8; i++) {
        long m = m0 + ty*8 + i;
#pragma unroll
        for (int j = 0; j < 8; j += 4) {
            int n = n0 + tx*8 + j;
            float4 o;
            o.x = acc[i][j]; o.y = acc[i][j+1]; o.z = acc[i][j+2]; o.w = acc[i][j+3];
            if (resid) {
                float4 rr = *(const float4*)(resid + m*(long)N + n);
                o.x = rr.x + scale*o.x; o.y = rr.y + scale*o.y;
                o.z = rr.z + scale*o.z; o.w = rr.w + scale*o.w;
            }
            *(float4*)(C + m*(long)N + n) = o;
        }
    }
}

// ------------------ fused conv(k=4) + S4D recurrence + sigmoid gate ------------
__global__ void __launch_bounds__(256) s4d_kernel(const float* __restrict__ conv_w,
                                                  const float* __restrict__ conv_b,
                                                  const float* __restrict__ ssm_D,
                                                  int li) {
    __shared__ float sP [NNt*NSv];
    __shared__ float sCF[NNt*NSv];
    int c = threadIdx.x;
    int b = blockIdx.x;
    for (int i = c; i < NNt*NSv; i += 256) {
        sP [i] = g_P [li*NNt*NSv + i];
        sCF[i] = g_CF[li*NNt*NSv + i];
    }
    float w0 = conv_w[c*4+0], w1 = conv_w[c*4+1], w2 = conv_w[c*4+2], w3 = conv_w[c*4+3];
    float cb = conv_b[c];
    float Dp = ssm_D[0];
    __syncthreads();

    float S[NSv];
#pragma unroll
    for (int i = 0; i < NSv; i++) S[i] = 0.0f;
    float x0 = 0.f, x1 = 0.f, x2 = 0.f, x3 = 0.f;

    const float* xzb = g_XZ + (long)b*NNt*(2*DIi);
    float*       yb  = g_Y  + (long)b*NNt*DIi;

    for (int l = 0; l < NNt; l++) {
        float xp = xzb[l*(2*DIi) + c];
        float zz = xzb[l*(2*DIi) + DIi + c];
        x0 = x1; x1 = x2; x2 = x3; x3 = xp;
        float xc = w0*x0 + w1*x1 + w2*x2 + w3*x3 + cb;

        const float4* p4 = (const float4*)&sP [l*NSv];
        const float4* f4 = (const float4*)&sCF[l*NSv];
        float ys = Dp * xc;
#pragma unroll
        for (int q = 0; q < 4; q++) {
            float4 p = p4[q], f = f4[q];
            S[q*4+0] += p.x*xc; ys += f.x*S[q*4+0];
            S[q*4+1] += p.y*xc; ys += f.y*S[q*4+1];
            S[q*4+2] += p.z*xc; ys += f.z*S[q*4+2];
            S[q*4+3] += p.w*xc; ys += f.w*S[q*4+3];
        }
        float sg = 1.0f / (1.0f + expf(-zz));
        yb[l*DIi + c] = ys * sg;
    }
}

// ------------------ final LN + normalize + importance MLP -> logits ------------
__global__ void __launch_bounds__(256) ftoken_kernel(const float* __restrict__ fin_g,
                                                     const float* __restrict__ fin_b,
                                                     const float* __restrict__ W1,
                                                     const float* __restrict__ b1,
                                                     const float* __restrict__ W2,
                                                     const float* __restrict__ b2,
                                                     float* __restrict__ out_tokens,
                                                     float* __restrict__ out_logits) {
    __shared__ float4 sW1[32*64];   // [k4][j]
    __shared__ float  sW2[64], sb1[64];
    __shared__ float  stn[8][132];
    int t = threadIdx.x;
    for (int f = t; f < 2048; f += 256) {
        int j = f >> 5, k4 = f & 31;
        sW1[k4*64 + j] = ((const float4*)W1)[f];
    }
    if (t < 64) { sW2[t] = W2[t]; sb1[t] = b1[t]; }
    __syncthreads();

    int lane = t & 31, w = t >> 5;
    long tk = (long)blockIdx.x * 8 + w;
    float4 v = *(const float4*)(g_X + tk*DD + lane*4);
    float s = v.x + v.y + v.z + v.w;
#pragma unroll
    for (int o = 16; o > 0; o >>= 1) s += __shfl_xor_sync(0xffffffffu, s, o);
    float m = s * (1.0f/DD);
    float d0 = v.x-m, d1 = v.y-m, d2 = v.z-m, d3 = v.w-m;
    float q = d0*d0 + d1*d1 + d2*d2 + d3*d3;
#pragma unroll
    for (int o = 16; o > 0; o >>= 1) q += __shfl_xor_sync(0xffffffffu, q, o);
    float r = rsqrtf(q * (1.0f/DD) + 1e-5f);
    float4 gg = *(const float4*)(fin_g + lane*4);
    float4 bb = *(const float4*)(fin_b + lane*4);
    float4 tok;
    tok.x = d0*r*gg.x + bb.x; tok.y = d1*r*gg.y + bb.y;
    tok.z = d2*r*gg.z + bb.z; tok.w = d3*r*gg.w + bb.w;
    *(float4*)(out_tokens + tk*DD + lane*4) = tok;

    float ss = tok.x*tok.x + tok.y*tok.y + tok.z*tok.z + tok.w*tok.w;
#pragma unroll
    for (int o = 16; o > 0; o >>= 1) ss += __shfl_xor_sync(0xffffffffu, ss, o);
    float rn = 1.0f / fmaxf(sqrtf(ss), 1e-6f);
    float4 tn4; tn4.x = tok.x*rn; tn4.y = tok.y*rn; tn4.z = tok.z*rn; tn4.w = tok.w*rn;
    *(float4*)&stn[w][lane*4] = tn4;
    __syncwarp();

    float h0 = sb1[lane], h1 = sb1[lane + 32];
#pragma unroll 8
    for (int k4 = 0; k4 < 32; k4++) {
        float4 tt = *(const float4*)&stn[w][k4*4];
        float4 wa = sW1[k4*64 + lane];
        float4 wb = sW1[k4*64 + lane + 32];
        h0 += tt.x*wa.x + tt.y*wa.y + tt.z*wa.z + tt.w*wa.w;
        h1 += tt.x*wb.x + tt.y*wb.y + tt.z*wb.z + tt.w*wb.w;
    }
    h0 = 0.5f*h0*(1.0f + erff(h0*0.70710678118654752f));
    h1 = 0.5f*h1*(1.0f + erff(h1*0.70710678118654752f));
    float gl = h0*sW2[lane] + h1*sW2[lane + 32];
#pragma unroll
    for (int o = 16; o > 0; o >>= 1) gl += __shfl_xor_sync(0xffffffffu, gl, o);
    if (lane == 0) out_logits[tk] = gl + b2[0];
}

// ------------------ softmax over N + weighted token pool -> feats --------------
__global__ void __launch_bounds__(256) fbatch_kernel(const float* __restrict__ logits,
                                                     const float* __restrict__ tokens,
                                                     float* __restrict__ out_w,
                                                     float* __restrict__ out_feats) {
    __shared__ float sw[NNt];
    __shared__ float red[8];
    int b = blockIdx.x, t = threadIdx.x, lane = t & 31, w = t >> 5;
    float lg = logits[(long)b*NNt + t];
    float mx = lg;
#pragma unroll
    for (int o = 16; o > 0; o >>= 1) mx = fmaxf(mx, __shfl_xor_sync(0xffffffffu, mx, o));
    if (lane == 0) red[w] = mx;
    __syncthreads();
    float bm = red[0];
#pragma unroll
    for (int i = 1; i < 8; i++) bm = fmaxf(bm, red[i]);
    float e = expf(lg - bm);
    float se = e;
#pragma unroll
    for (int o = 16; o > 0; o >>= 1) se += __shfl_xor_sync(0xffffffffu, se, o);
    __syncthreads();
    if (lane == 0) red[w] = se;
    __syncthreads();
    float tot = 0.f;
#pragma unroll
    for (int i = 0; i < 8; i++) tot += red[i];
    float wv = e / tot;
    out_w[(long)b*NNt + t] = wv;
    sw[t] = wv;
    __syncthreads();
    if (t < DD) {
        float acc = 0.f;
        for (int n = 0; n < NNt; n++)
            acc += sw[n] * tokens[((long)b*NNt + n)*DD + t];
        out_feats[b*DD + t] = acc;
    }
}

// ------------------ three linear heads -----------------------------------------
__global__ void __launch_bounds__(192) heads_kernel(const float* __restrict__ feats,
        const float* __restrict__ texW, const float* __restrict__ texb,
        const float* __restrict__ edgeW, const float* __restrict__ edgeb,
        const float* __restrict__ strW, const float* __restrict__ strb,
        float* __restrict__ o_tex, float* __restrict__ o_edge, float* __restrict__ o_str) {
    __shared__ float sf[DD];
    int b = blockIdx.x, t = threadIdx.x;
    if (t < DD) sf[t] = feats[b*DD + t];
    __syncthreads();
    int head = t / 64, j = t % 64;
    const float* W  = (head == 0) ? texW : (head == 1) ? edgeW : strW;
    const float* bi = (head == 0) ? texb : (head == 1) ? edgeb : strb;
    float acc = bi[j];
#pragma unroll 4
    for (int k = 0; k < DD; k++) acc += sf[k] * W[j*DD + k];
    float* o = (head == 0) ? o_tex : (head == 1) ? o_edge : o_str;
    o[b*64 + j] = acc;
}

// ------------------ launch ------------------------------------------------------
extern "C" void kernel_launch(void* const* d_in, const int* in_sizes, int n_in,
                              void* d_out, int out_size) {
    const float* tokens_in = (const float*)d_in[0];
    const float* pos       = (const float*)d_in[1];
    const float* ln_g      = (const float*)d_in[2];
    const float* ln_b      = (const float*)d_in[3];
    const float* W_in      = (const float*)d_in[4];
    const float* conv_w    = (const float*)d_in[5];
    const float* conv_b    = (const float*)d_in[6];
    const float* ssm_B     = (const float*)d_in[7];
    const float* ssm_C     = (const float*)d_in[8];
    const float* log_dt    = (const float*)d_in[9];
    const float* ssm_D     = (const float*)d_in[10];
    const float* W_out     = (const float*)d_in[11];
    const float* res_scale = (const float*)d_in[12];
    const float* fin_g     = (const float*)d_in[13];
    const float* fin_b     = (const float*)d_in[14];
    const float* W1        = (const float*)d_in[15];
    const float* b1        = (const float*)d_in[16];
    const float* W2        = (const float*)d_in[17];
    const float* b2        = (const float*)d_in[18];
    const float* texW      = (const float*)d_in[19];
    const float* texb      = (const float*)d_in[20];
    const float* edgeW     = (const float*)d_in[21];
    const float* edgeb     = (const float*)d_in[22];
    const float* strW      = (const float*)d_in[23];
    const float* strb      = (const float*)d_in[24];

    float *pX, *pH, *pXZ, *pY;
    cudaGetSymbolAddress((void**)&pX,  g_X);
    cudaGetSymbolAddress((void**)&pH,  g_H);
    cudaGetSymbolAddress((void**)&pXZ, g_XZ);
    cudaGetSymbolAddress((void**)&pY,  g_Y);

    float* out     = (float*)d_out;
    float* o_feats = out;
    float* o_tex   = o_feats + (long)BB*DD;
    float* o_edge  = o_tex   + (long)BB*64;
    float* o_str   = o_edge  + (long)BB*64;
    float* o_tok   = o_str   + (long)BB*64;
    float* o_w     = o_tok   + (long)BB*NNt*DD;

    const long M = (long)BB * NNt;

    prep_kernel<<<NLv, NNt>>>(ssm_B, ssm_C, log_dt);
    ln_kernel<<<(unsigned)(M/4), 128>>>(tokens_in, pos, ln_g, ln_b, 1);
    for (int li = 0; li < NLv; li++) {
        if (li > 0)
            ln_kernel<<<(unsigned)(M/4), 128>>>(pX, nullptr, ln_g + li*DD, ln_b + li*DD, 0);
        gemm_kernel<<<dim3((unsigned)(M/128), 4), 256>>>(
            pH, W_in + (long)li*2*DIi*DD, pXZ, DD, 2*DIi, nullptr, nullptr);
        s4d_kernel<<<BB, DIi>>>(conv_w + li*DIi*4, conv_b + li*DIi, ssm_D + li, li);
        gemm_kernel<<<dim3((unsigned)(M/128), 1), 256>>>(
            pY, W_out + (long)li*DD*DIi, pX, DIi, DD, pX, res_scale + li);
    }
    ftoken_kernel<<<(unsigned)(M/8), 256>>>(fin_g, fin_b, W1, b1, W2, b2, o_tok, pH);
    fbatch_kernel<<<BB, NNt>>>(pH, o_tok, o_w, o_feats);
    heads_kernel<<<BB, 192>>>(o_feats, texW, texb, edgeW, edgeb, strW, strb,
                              o_tex, o_edge, o_str);
}

// round 5
// speedup vs baseline: 1.3637x; 1.3637x over previous
#include <cuda_runtime.h>
#include <cuda_bf16.h>
#include <mma.h>
#include <math.h>
#include <stdint.h>

using namespace nvcuda;

#define BB  512
#define NNt 256
#define DD  128
#define DIi 256
#define NLv 4
#define NSv 16
#define MT  (BB*NNt)

#define LDT   136      // bf16 smem tile leading dim (128 + 8)
#define LDST  132      // fp32 stage leading dim

// ------------------ scratch (device globals; no allocation) ------------------
__device__ float g_X [MT*DD];            // residual stream (fp32)
__device__ float g_XZ[MT*2*DIi];         // in-proj output (fp32); reused for logits
__device__ __nv_bfloat16 g_Hhi[MT*DD],  g_Hlo[MT*DD];    // LN out split
__device__ __nv_bfloat16 g_Yhi[MT*DIi], g_Ylo[MT*DIi];   // gated ssm out split
__device__ __nv_bfloat16 g_Wih[NLv*2*DIi*DD], g_Wil[NLv*2*DIi*DD];
__device__ __nv_bfloat16 g_Woh[NLv*DD*DIi],   g_Wol[NLv*DD*DIi];
__device__ float g_P [NLv*NNt*NSv];
__device__ float g_CF[NLv*NNt*NSv];

// ------------------ per-layer SSM coefficient tables ------------------
__global__ void prep_kernel(const float* __restrict__ ssm_B,
                            const float* __restrict__ ssm_C,
                            const float* __restrict__ log_dt) {
    int li = blockIdx.x;
    int l  = threadIdx.x;
    float dt = expf(log_dt[li]);
    dt = fminf(fmaxf(dt, 1e-4f), 1.0f);
    for (int n = 0; n < NSv; n++) {
        float A  = -(float)(n + 1);
        float t  = fminf(fmaxf(dt * A, -10.0f), 10.0f);
        float dA = expf(t);
        float dB = (dA - 1.0f) / fminf(A, -1e-4f) * ssm_B[li*NSv + n];
        g_P [(li*NNt + l)*NSv + n] = expf((float)l * t);
        g_CF[(li*NNt + l)*NSv + n] = ssm_C[li*NSv + n] * dB * expf((float)(NNt - 1 - l) * t);
    }
}

// ------------------ fp32 -> bf16 hi/lo weight split ------------------
__global__ void wsplit_kernel(const float* __restrict__ src,
                              __nv_bfloat16* __restrict__ hi,
                              __nv_bfloat16* __restrict__ lo, int n) {
    int i = blockIdx.x * 256 + threadIdx.x;
    if (i < n) {
        float w = src[i];
        __nv_bfloat16 h = __float2bfloat16_rn(w);
        hi[i] = h;
        lo[i] = __float2bfloat16_rn(w - __bfloat162float(h));
    }
}

// ------------------ LayerNorm -> bf16 hi/lo (warp per token) ------------------
__global__ void __launch_bounds__(128) ln_kernel(const float* __restrict__ in,
                                                 const float* __restrict__ pos,
                                                 const float* __restrict__ g,
                                                 const float* __restrict__ b,
                                                 int addPos) {
    int lane = threadIdx.x & 31, w = threadIdx.x >> 5;
    long tk = (long)blockIdx.x * 4 + w;
    float4 v = *(const float4*)(in + tk*DD + lane*4);
    if (addPos) {
        int n = (int)(tk % NNt);
        float4 p = *(const float4*)(pos + (long)n*DD + lane*4);
        v.x += p.x; v.y += p.y; v.z += p.z; v.w += p.w;
        *(float4*)(g_X + tk*DD + lane*4) = v;
    }
    float s = v.x + v.y + v.z + v.w;
#pragma unroll
    for (int o = 16; o > 0; o >>= 1) s += __shfl_xor_sync(0xffffffffu, s, o);
    float m = s * (1.0f/DD);
    float d0 = v.x-m, d1 = v.y-m, d2 = v.z-m, d3 = v.w-m;
    float q = d0*d0 + d1*d1 + d2*d2 + d3*d3;
#pragma unroll
    for (int o = 16; o > 0; o >>= 1) q += __shfl_xor_sync(0xffffffffu, q, o);
    float r = rsqrtf(q * (1.0f/DD) + 1e-5f);
    float4 gg = *(const float4*)(g + lane*4);
    float4 bb = *(const float4*)(b + lane*4);
    float ov[4];
    ov[0] = d0*r*gg.x + bb.x; ov[1] = d1*r*gg.y + bb.y;
    ov[2] = d2*r*gg.z + bb.z; ov[3] = d3*r*gg.w + bb.w;
    __nv_bfloat16 h[4], l2[4];
#pragma unroll
    for (int i = 0; i < 4; i++) {
        h[i]  = __float2bfloat16_rn(ov[i]);
        l2[i] = __float2bfloat16_rn(ov[i] - __bfloat162float(h[i]));
    }
    __nv_bfloat162* dh = (__nv_bfloat162*)(g_Hhi + tk*DD + lane*4);
    __nv_bfloat162* dl = (__nv_bfloat162*)(g_Hlo + tk*DD + lane*4);
    dh[0] = __nv_bfloat162{h[0], h[1]};  dh[1] = __nv_bfloat162{h[2], h[3]};
    dl[0] = __nv_bfloat162{l2[0], l2[1]}; dl[1] = __nv_bfloat162{l2[2], l2[3]};
}

// ------------------ WMMA bf16 GEMM: C[m,n] = sum_k A[m,k]*B[n,k] ---------------
// A = Ahi+Alo, B = Bhi+Blo (bf16 splits); products hh+hl+lh in one fp32 acc.
// CTA: 128 x 128 per nb. 8 warps: 4 (m) x 2 (n); warp tile 32 x 64.
__global__ void __launch_bounds__(256, 1)
gemm_wmma_kernel(const __nv_bfloat16* __restrict__ Ahi, const __nv_bfloat16* __restrict__ Alo,
                 const __nv_bfloat16* __restrict__ Bhi, const __nv_bfloat16* __restrict__ Blo,
                 float* __restrict__ C, int K, int NB, int Ntot,
                 const float* __restrict__ resid, const float* __restrict__ rs) {
    extern __shared__ char sm[];
    __nv_bfloat16* As_hi = (__nv_bfloat16*)sm;           // 128 x LDT
    __nv_bfloat16* As_lo = As_hi + 128*LDT;
    __nv_bfloat16* Bs_hi = As_lo + 128*LDT;
    __nv_bfloat16* Bs_lo = Bs_hi + 128*LDT;
    float* stage = (float*)Bs_hi;                        // reuse B region (128 x LDST)

    int t = threadIdx.x;
    int warp = t >> 5;
    int wm = warp & 3;            // m-warp: rows wm*32 .. +31
    int wn = warp >> 2;           // n-warp: cols wn*64 .. +63
    long m0 = (long)blockIdx.x * 128;
    const int KH = K >> 7;

    float sc = 0.0f;
    if (resid) sc = fminf(fmaxf(rs[0], 0.0f), 1.5f);

    for (int nb = 0; nb < NB; nb++) {
        long n0 = (long)nb * 128;
        wmma::fragment<wmma::accumulator, 16, 16, 16, float> acc[2][4];
#pragma unroll
        for (int i = 0; i < 2; i++)
#pragma unroll
            for (int j = 0; j < 4; j++) wmma::fill_fragment(acc[i][j], 0.0f);

        for (int kh = 0; kh < KH; kh++) {
            int kb = kh * 128;
            __syncthreads();
            // load tiles: 2048 16B-chunks each (row = g>>4, c16 = g&15)
            if (nb == 0 || KH > 1) {
#pragma unroll
                for (int u = 0; u < 8; u++) {
                    int g2 = t + u*256;
                    int r = g2 >> 4, c16 = g2 & 15;
                    *(uint4*)((char*)As_hi + r*(LDT*2) + c16*16) =
                        *(const uint4*)(Ahi + (m0 + r)*(long)K + kb + c16*8);
                    *(uint4*)((char*)As_lo + r*(LDT*2) + c16*16) =
                        *(const uint4*)(Alo + (m0 + r)*(long)K + kb + c16*8);
                }
            }
#pragma unroll
            for (int u = 0; u < 8; u++) {
                int g2 = t + u*256;
                int r = g2 >> 4, c16 = g2 & 15;
                *(uint4*)((char*)Bs_hi + r*(LDT*2) + c16*16) =
                    *(const uint4*)(Bhi + (n0 + r)*(long)K + kb + c16*8);
                *(uint4*)((char*)Bs_lo + r*(LDT*2) + c16*16) =
                    *(const uint4*)(Blo + (n0 + r)*(long)K + kb + c16*8);
            }
            __syncthreads();

#pragma unroll
            for (int ks = 0; ks < 8; ks++) {
                wmma::fragment<wmma::matrix_a, 16, 16, 16, __nv_bfloat16, wmma::row_major> ah[2], al[2];
                wmma::fragment<wmma::matrix_b, 16, 16, 16, __nv_bfloat16, wmma::col_major> bh[4], bl[4];
#pragma unroll
                for (int i = 0; i < 2; i++) {
                    wmma::load_matrix_sync(ah[i], As_hi + (wm*32 + i*16)*LDT + ks*16, LDT);
                    wmma::load_matrix_sync(al[i], As_lo + (wm*32 + i*16)*LDT + ks*16, LDT);
                }
#pragma unroll
                for (int j = 0; j < 4; j++) {
                    wmma::load_matrix_sync(bh[j], Bs_hi + (wn*64 + j*16)*LDT + ks*16, LDT);
                    wmma::load_matrix_sync(bl[j], Bs_lo + (wn*64 + j*16)*LDT + ks*16, LDT);
                }
#pragma unroll
                for (int i = 0; i < 2; i++)
#pragma unroll
                    for (int j = 0; j < 4; j++) {
                        wmma::mma_sync(acc[i][j], ah[i], bh[j], acc[i][j]);
                        wmma::mma_sync(acc[i][j], ah[i], bl[j], acc[i][j]);
                        wmma::mma_sync(acc[i][j], al[i], bh[j], acc[i][j]);
                    }
            }
        }

        // epilogue: frags -> smem stage -> coalesced gmem (+resid)
        __syncthreads();
#pragma unroll
        for (int i = 0; i < 2; i++)
#pragma unroll
            for (int j = 0; j < 4; j++)
                wmma::store_matrix_sync(stage + (wm*32 + i*16)*LDST + wn*64 + j*16,
                                        acc[i][j], LDST, wmma::mem_row_major);
        __syncthreads();
#pragma unroll
        for (int u = 0; u < 16; u++) {
            int id = t + u*256;              // 4096 float4
            int row = id >> 5, q = id & 31;
            float4 v;
            v.x = stage[row*LDST + q*4 + 0]; v.y = stage[row*LDST + q*4 + 1];
            v.z = stage[row*LDST + q*4 + 2]; v.w = stage[row*LDST + q*4 + 3];
            long m = m0 + row;
            int col = (int)n0 + q*4;
            if (resid) {
                float4 rr = *(const float4*)(resid + m*(long)Ntot + col);
                v.x = rr.x + sc*v.x; v.y = rr.y + sc*v.y;
                v.z = rr.z + sc*v.z; v.w = rr.w + sc*v.w;
            }
            *(float4*)(C + m*(long)Ntot + col) = v;
        }
    }
}

// ------------------ fused conv(k=4) + S4D recurrence + sigmoid gate ------------
__global__ void __launch_bounds__(256) s4d_kernel(const float* __restrict__ conv_w,
                                                  const float* __restrict__ conv_b,
                                                  const float* __restrict__ ssm_D,
                                                  int li) {
    __shared__ float sP [NNt*NSv];
    __shared__ float sCF[NNt*NSv];
    int c = threadIdx.x;
    int b = blockIdx.x;
    for (int i = c; i < NNt*NSv; i += 256) {
        sP [i] = g_P [li*NNt*NSv + i];
        sCF[i] = g_CF[li*NNt*NSv + i];
    }
    float w0 = conv_w[c*4+0], w1 = conv_w[c*4+1], w2 = conv_w[c*4+2], w3 = conv_w[c*4+3];
    float cb = conv_b[c];
    float Dp = ssm_D[0];
    __syncthreads();

    float S[NSv];
#pragma unroll
    for (int i = 0; i < NSv; i++) S[i] = 0.0f;
    float x0 = 0.f, x1 = 0.f, x2 = 0.f, x3 = 0.f;

    const float* xzb = g_XZ + (long)b*NNt*(2*DIi);
    __nv_bfloat16* yh = g_Yhi + (long)b*NNt*DIi;
    __nv_bfloat16* yl = g_Ylo + (long)b*NNt*DIi;

#pragma unroll 2
    for (int l = 0; l < NNt; l++) {
        float xp = xzb[l*(2*DIi) + c];
        float zz = xzb[l*(2*DIi) + DIi + c];
        x0 = x1; x1 = x2; x2 = x3; x3 = xp;
        float xc = fmaf(w0, x0, fmaf(w1, x1, fmaf(w2, x2, fmaf(w3, x3, cb))));

        const float4* p4 = (const float4*)&sP [l*NSv];
        const float4* f4 = (const float4*)&sCF[l*NSv];
        float ys0 = Dp * xc, ys1 = 0.f, ys2 = 0.f, ys3 = 0.f;
#pragma unroll
        for (int q = 0; q < 4; q++) {
            float4 p = p4[q], f = f4[q];
            S[q*4+0] = fmaf(p.x, xc, S[q*4+0]); ys0 = fmaf(f.x, S[q*4+0], ys0);
            S[q*4+1] = fmaf(p.y, xc, S[q*4+1]); ys1 = fmaf(f.y, S[q*4+1], ys1);
            S[q*4+2] = fmaf(p.z, xc, S[q*4+2]); ys2 = fmaf(f.z, S[q*4+2], ys2);
            S[q*4+3] = fmaf(p.w, xc, S[q*4+3]); ys3 = fmaf(f.w, S[q*4+3], ys3);
        }
        float ys = (ys0 + ys1) + (ys2 + ys3);
        float e  = __expf(-zz);
        float yv = ys / (1.0f + e);
        __nv_bfloat16 h = __float2bfloat16_rn(yv);
        yh[l*DIi + c] = h;
        yl[l*DIi + c] = __float2bfloat16_rn(yv - __bfloat162float(h));
    }
}

// ------------------ final LN + normalize + importance MLP -> logits ------------
__global__ void __launch_bounds__(256) ftoken_kernel(const float* __restrict__ fin_g,
                                                     const float* __restrict__ fin_b,
                                                     const float* __restrict__ W1,
                                                     const float* __restrict__ b1,
                                                     const float* __restrict__ W2,
                                                     const float* __restrict__ b2,
                                                     float* __restrict__ out_tokens,
                                                     float* __restrict__ out_logits) {
    __shared__ float4 sW1[32*64];
    __shared__ float  sW2[64], sb1[64];
    __shared__ float  stn[8][132];
    int t = threadIdx.x;
    for (int f = t; f < 2048; f += 256) {
        int j = f >> 5, k4 = f & 31;
        sW1[k4*64 + j] = ((const float4*)W1)[f];
    }
    if (t < 64) { sW2[t] = W2[t]; sb1[t] = b1[t]; }
    __syncthreads();

    int lane = t & 31, w = t >> 5;
    long tk = (long)blockIdx.x * 8 + w;
    float4 v = *(const float4*)(g_X + tk*DD + lane*4);
    float s = v.x + v.y + v.z + v.w;
#pragma unroll
    for (int o = 16; o > 0; o >>= 1) s += __shfl_xor_sync(0xffffffffu, s, o);
    float m = s * (1.0f/DD);
    float d0 = v.x-m, d1 = v.y-m, d2 = v.z-m, d3 = v.w-m;
    float q = d0*d0 + d1*d1 + d2*d2 + d3*d3;
#pragma unroll
    for (int o = 16; o > 0; o >>= 1) q += __shfl_xor_sync(0xffffffffu, q, o);
    float r = rsqrtf(q * (1.0f/DD) + 1e-5f);
    float4 gg = *(const float4*)(fin_g + lane*4);
    float4 bb = *(const float4*)(fin_b + lane*4);
    float4 tok;
    tok.x = d0*r*gg.x + bb.x; tok.y = d1*r*gg.y + bb.y;
    tok.z = d2*r*gg.z + bb.z; tok.w = d3*r*gg.w + bb.w;
    *(float4*)(out_tokens + tk*DD + lane*4) = tok;

    float ss = tok.x*tok.x + tok.y*tok.y + tok.z*tok.z + tok.w*tok.w;
#pragma unroll
    for (int o = 16; o > 0; o >>= 1) ss += __shfl_xor_sync(0xffffffffu, ss, o);
    float rn = 1.0f / fmaxf(sqrtf(ss), 1e-6f);
    float4 tn4; tn4.x = tok.x*rn; tn4.y = tok.y*rn; tn4.z = tok.z*rn; tn4.w = tok.w*rn;
    *(float4*)&stn[w][lane*4] = tn4;
    __syncwarp();

    float h0 = sb1[lane], h1 = sb1[lane + 32];
#pragma unroll 8
    for (int k4 = 0; k4 < 32; k4++) {
        float4 tt = *(const float4*)&stn[w][k4*4];
        float4 wa = sW1[k4*64 + lane];
        float4 wb = sW1[k4*64 + lane + 32];
        h0 += tt.x*wa.x + tt.y*wa.y + tt.z*wa.z + tt.w*wa.w;
        h1 += tt.x*wb.x + tt.y*wb.y + tt.z*wb.z + tt.w*wb.w;
    }
    h0 = 0.5f*h0*(1.0f + erff(h0*0.70710678118654752f));
    h1 = 0.5f*h1*(1.0f + erff(h1*0.70710678118654752f));
    float gl = h0*sW2[lane] + h1*sW2[lane + 32];
#pragma unroll
    for (int o = 16; o > 0; o >>= 1) gl += __shfl_xor_sync(0xffffffffu, gl, o);
    if (lane == 0) out_logits[tk] = gl + b2[0];
}

// ------------------ softmax over N + weighted token pool -> feats --------------
__global__ void __launch_bounds__(256) fbatch_kernel(const float* __restrict__ logits,
                                                     const float* __restrict__ tokens,
                                                     float* __restrict__ out_w,
                                                     float* __restrict__ out_feats) {
    __shared__ float sw[NNt];
    __shared__ float red[8];
    int b = blockIdx.x, t = threadIdx.x, lane = t & 31, w = t >> 5;
    float lg = logits[(long)b*NNt + t];
    float mx = lg;
#pragma unroll
    for (int o = 16; o > 0; o >>= 1) mx = fmaxf(mx, __shfl_xor_sync(0xffffffffu, mx, o));
    if (lane == 0) red[w] = mx;
    __syncthreads();
    float bm = red[0];
#pragma unroll
    for (int i = 1; i < 8; i++) bm = fmaxf(bm, red[i]);
    float e = expf(lg - bm);
    float se = e;
#pragma unroll
    for (int o = 16; o > 0; o >>= 1) se += __shfl_xor_sync(0xffffffffu, se, o);
    __syncthreads();
    if (lane == 0) red[w] = se;
    __syncthreads();
    float tot = 0.f;
#pragma unroll
    for (int i = 0; i < 8; i++) tot += red[i];
    float wv = e / tot;
    out_w[(long)b*NNt + t] = wv;
    sw[t] = wv;
    __syncthreads();
    if (t < DD) {
        float acc = 0.f;
        for (int n = 0; n < NNt; n++)
            acc += sw[n] * tokens[((long)b*NNt + n)*DD + t];
        out_feats[b*DD + t] = acc;
    }
}

// ------------------ three linear heads -----------------------------------------
__global__ void __launch_bounds__(192) heads_kernel(const float* __restrict__ feats,
        const float* __restrict__ texW, const float* __restrict__ texb,
        const float* __restrict__ edgeW, const float* __restrict__ edgeb,
        const float* __restrict__ strW, const float* __restrict__ strb,
        float* __restrict__ o_tex, float* __restrict__ o_edge, float* __restrict__ o_str) {
    __shared__ float sf[DD];
    int b = blockIdx.x, t = threadIdx.x;
    if (t < DD) sf[t] = feats[b*DD + t];
    __syncthreads();
    int head = t / 64, j = t % 64;
    const float* W  = (head == 0) ? texW : (head == 1) ? edgeW : strW;
    const float* bi = (head == 0) ? texb : (head == 1) ? edgeb : strb;
    float acc = bi[j];
#pragma unroll 4
    for (int k = 0; k < DD; k++) acc += sf[k] * W[j*DD + k];
    float* o = (head == 0) ? o_tex : (head == 1) ? o_edge : o_str;
    o[b*64 + j] = acc;
}

// ------------------ launch ------------------------------------------------------
extern "C" void kernel_launch(void* const* d_in, const int* in_sizes, int n_in,
                              void* d_out, int out_size) {
    const float* tokens_in = (const float*)d_in[0];
    const float* pos       = (const float*)d_in[1];
    const float* ln_g      = (const float*)d_in[2];
    const float* ln_b      = (const float*)d_in[3];
    const float* W_in      = (const float*)d_in[4];
    const float* conv_w    = (const float*)d_in[5];
    const float* conv_b    = (const float*)d_in[6];
    const float* ssm_B     = (const float*)d_in[7];
    const float* ssm_C     = (const float*)d_in[8];
    const float* log_dt    = (const float*)d_in[9];
    const float* ssm_D     = (const float*)d_in[10];
    const float* W_out     = (const float*)d_in[11];
    const float* res_scale = (const float*)d_in[12];
    const float* fin_g     = (const float*)d_in[13];
    const float* fin_b     = (const float*)d_in[14];
    const float* W1        = (const float*)d_in[15];
    const float* b1        = (const float*)d_in[16];
    const float* W2        = (const float*)d_in[17];
    const float* b2        = (const float*)d_in[18];
    const float* texW      = (const float*)d_in[19];
    const float* texb      = (const float*)d_in[20];
    const float* edgeW     = (const float*)d_in[21];
    const float* edgeb     = (const float*)d_in[22];
    const float* strW      = (const float*)d_in[23];
    const float* strb      = (const float*)d_in[24];

    float *pX, *pXZ;
    __nv_bfloat16 *pHh, *pHl, *pYh, *pYl, *pWih, *pWil, *pWoh, *pWol;
    cudaGetSymbolAddress((void**)&pX,   g_X);
    cudaGetSymbolAddress((void**)&pXZ,  g_XZ);
    cudaGetSymbolAddress((void**)&pHh,  g_Hhi);
    cudaGetSymbolAddress((void**)&pHl,  g_Hlo);
    cudaGetSymbolAddress((void**)&pYh,  g_Yhi);
    cudaGetSymbolAddress((void**)&pYl,  g_Ylo);
    cudaGetSymbolAddress((void**)&pWih, g_Wih);
    cudaGetSymbolAddress((void**)&pWil, g_Wil);
    cudaGetSymbolAddress((void**)&pWoh, g_Woh);
    cudaGetSymbolAddress((void**)&pWol, g_Wol);

    const int SMEMB = 4 * 128 * LDT * 2;   // 4 bf16 tiles, 139264 B
    cudaFuncSetAttribute(gemm_wmma_kernel,
                         cudaFuncAttributeMaxDynamicSharedMemorySize, SMEMB);

    float* out     = (float*)d_out;
    float* o_feats = out;
    float* o_tex   = o_feats + (long)BB*DD;
    float* o_edge  = o_tex   + (long)BB*64;
    float* o_str   = o_edge  + (long)BB*64;
    float* o_tok   = o_str   + (long)BB*64;
    float* o_w     = o_tok   + (long)BB*NNt*DD;

    const long M = (long)MT;

    prep_kernel<<<NLv, NNt>>>(ssm_B, ssm_C, log_dt);
    wsplit_kernel<<<(NLv*2*DIi*DD + 255)/256, 256>>>(W_in,  pWih, pWil, NLv*2*DIi*DD);
    wsplit_kernel<<<(NLv*DD*DIi   + 255)/256, 256>>>(W_out, pWoh, pWol, NLv*DD*DIi);
    ln_kernel<<<(unsigned)(M/4), 128>>>(tokens_in, pos, ln_g, ln_b, 1);
    for (int li = 0; li < NLv; li++) {
        if (li > 0)
            ln_kernel<<<(unsigned)(M/4), 128>>>(pX, nullptr, ln_g + li*DD, ln_b + li*DD, 0);
        gemm_wmma_kernel<<<(unsigned)(M/128), 256, SMEMB>>>(
            pHh, pHl, pWih + (long)li*2*DIi*DD, pWil + (long)li*2*DIi*DD,
            pXZ, DD, 4, 2*DIi, nullptr, nullptr);
        s4d_kernel<<<BB, DIi>>>(conv_w + li*DIi*4, conv_b + li*DIi, ssm_D + li, li);
        gemm_wmma_kernel<<<(unsigned)(M/128), 256, SMEMB>>>(
            pYh, pYl, pWoh + (long)li*DD*DIi, pWol + (long)li*DD*DIi,
            pX, DIi, 1, DD, pX, res_scale + li);
    }
    ftoken_kernel<<<(unsigned)(M/8), 256>>>(fin_g, fin_b, W1, b1, W2, b2, o_tok, pXZ);
    fbatch_kernel<<<BB, NNt>>>(pXZ, o_tok, o_w, o_feats);
    heads_kernel<<<BB, 192>>>(o_feats, texW, texb, edgeW, edgeb, strW, strb,
                              o_tex, o_edge, o_str);
}